// round 9
// baseline (speedup 1.0000x reference)
#include <cuda_runtime.h>
#include <cstdint>

// YOLOv1 loss — single fused kernel.
// R9: R2 structure (block-coalesced cp.async, 2 stages, direct-smem compute)
// with TILE=98 / grid=512: 802816 cells = 98*8192 tiles = 512 CTAs * 16 tiles
// exactly -> zero remainder, zero ragged tail. 47 KB smem -> 4 CTAs/SM.

#define TPB   128
#define TILE  98
#define NF4   (TILE * 30 / 4)             // 735 float4 per tensor per stage
#define TEN_B (NF4 * 16)                  // 11760 B per tensor
#define STAGE_BYTES (2 * TEN_B)           // 23520 B (pred + target)
#define NSTAGE 2
#define SMEM_BYTES (NSTAGE * STAGE_BYTES) // 47040 B
#define GRID_MAX 1536

__device__ float g_partials[GRID_MAX * 5];
__device__ unsigned int g_ticket = 0;

__device__ __forceinline__ void cp16(unsigned dst, const void* src) {
    asm volatile("cp.async.cg.shared.global [%0], [%1], 16;" :: "r"(dst), "l"(src));
}

__device__ __forceinline__ float iou_fn(float bx, float by, float bw, float bh,
                                        float tx, float ty, float tw, float th)
{
    float ax1 = bx - bw * 0.5f, ay1 = by - bh * 0.5f;
    float ax2 = bx + bw * 0.5f, ay2 = by + bh * 0.5f;
    float cx1 = tx - tw * 0.5f, cy1 = ty - th * 0.5f;
    float cx2 = tx + tw * 0.5f, cy2 = ty + th * 0.5f;
    float iw = fmaxf(fminf(ax2, cx2) - fmaxf(ax1, cx1), 0.0f);
    float ih = fmaxf(fminf(ay2, cy2) - fmaxf(ay1, cy1), 0.0f);
    float inter = iw * ih;
    float uni = bw * bh + tw * th - inter;
    return inter / fmaxf(uni, 1e-10f);
}

// Per-cell loss update reading DIRECTLY from (shared or global) memory.
// Dynamic final index -> LDS/LDG, never local memory.
__device__ __forceinline__ void cell_update(const float* P, const float* T,
                                            float& a0, float& a1, float& a2,
                                            float& a3, float& a4)
{
    float t4v  = T[4];
    float objf = (t4v == 1.0f) ? 1.0f : 0.0f;
    float noobjf = 1.0f - objf;

    float tx = T[0], ty = T[1], tw = T[2], th = T[3];
    float i0 = iou_fn(P[0], P[1], P[2], P[3], tx, ty, tw, th);
    float i1 = iou_fn(P[5], P[6], P[7], P[8], tx, ty, tw, th);

    bool b0 = (i0 > i1);   // ties -> box 1 (matches jnp.where)
    float wx = b0 ? P[0] : P[5];
    float wy = b0 ? P[1] : P[6];
    float ww = b0 ? P[2] : P[7];
    float wh = b0 ? P[3] : P[8];
    float wc = b0 ? P[4] : P[9];
    float wiou = fmaxf(i0, i1);

    float dx = wx - tx, dy = wy - ty;
    float dw = sqrtf(ww) - sqrtf(tw);
    float dh = sqrtf(wh) - sqrtf(th);
    a0 += (dx * dx + dy * dy + dw * dw + dh * dh) * objf;

    float dc = wc - wiou;
    a1 += dc * dc * objf;

    float d4 = P[4] - t4v;
    float d9 = P[9] - T[9];
    a2 += (d4 * d4 + d9 * d9) * noobjf;

    float m = -1e30f;
    #pragma unroll
    for (int c = 0; c < 20; c++) m = fmaxf(m, P[10 + c]);
    float sum = 0.0f;
    #pragma unroll
    for (int c = 0; c < 20; c++) sum += __expf(P[10 + c] - m);
    float tm = -1e30f; int targc = 0;
    #pragma unroll
    for (int c = 0; c < 20; c++) {
        float v = T[10 + c];
        if (v > tm) { tm = v; targc = c; }   // first-occurrence argmax
    }
    float ce = m + __logf(sum) - P[10 + targc];
    a3 += ce * objf;
    a4 += objf;
}

extern __shared__ char dynbuf[];   // NSTAGE x STAGE_BYTES

__global__ __launch_bounds__(TPB)
void yolo_fused_kernel(const float* __restrict__ pred,
                       const float* __restrict__ target,
                       int n_cells, float invB,
                       float* __restrict__ out)
{
    const int tid = threadIdx.x;
    const int nb  = gridDim.x;
    const long long ntiles = n_cells / TILE;
    const int rem = n_cells - (int)(ntiles * TILE);   // 0 for the bench shape

    __shared__ float sred[5][TPB / 32];
    __shared__ int amLast;

    float acc0 = 0.f, acc1 = 0.f, acc2 = 0.f, acc3 = 0.f, acc4 = 0.f;

    // Remainder cells (generic safety; 0 for the bench shape).
    if (rem && blockIdx.x == 0 && tid < rem) {
        long long c0 = ntiles * TILE + tid;
        cell_update(pred + c0 * 30, target + c0 * 30,
                    acc0, acc1, acc2, acc3, acc4);
    }

    const unsigned sbase = (unsigned)__cvta_generic_to_shared(dynbuf);

    const long long t0 = blockIdx.x;
    long long niter = 0;
    if (t0 < ntiles) niter = (ntiles - t0 + nb - 1) / nb;

    auto issue = [&](long long idx, int s) {
        long long t = t0 + idx * nb;
        const float4* p4 = (const float4*)(pred   + t * (TILE * 30));
        const float4* t4 = (const float4*)(target + t * (TILE * 30));
        unsigned base = sbase + (unsigned)(s * STAGE_BYTES);
        #pragma unroll 3
        for (int i = tid; i < NF4; i += TPB) {
            cp16(base + 16u * i,                   p4 + i);
            cp16(base + (unsigned)TEN_B + 16u * i, t4 + i);
        }
        asm volatile("cp.async.commit_group;");
    };

    // prologue: fill both stages
    if (niter > 0) issue(0, 0);
    if (niter > 1) issue(1, 1);

    for (long long it = 0; it < niter; ++it) {
        long long left = niter - 1 - it;   // groups issued beyond this one
        if (left >= 1) asm volatile("cp.async.wait_group 1;");
        else           asm volatile("cp.async.wait_group 0;");
        __syncthreads();

        int s = (int)(it & 1);
        if (tid < TILE) {
            const float* sp = (const float*)(dynbuf + (size_t)s * STAGE_BYTES);
            const float* P = sp + tid * 30;
            const float* T = sp + (TEN_B / 4) + tid * 30;
            cell_update(P, T, acc0, acc1, acc2, acc3, acc4);
        }
        __syncthreads();

        long long nxt = it + 2;
        if (nxt < niter) issue(nxt, s);    // refill the stage just consumed
    }

    // ---- deterministic in-block reduction ----
    const unsigned mask = 0xffffffffu;
    #pragma unroll
    for (int off = 16; off; off >>= 1) {
        acc0 += __shfl_down_sync(mask, acc0, off);
        acc1 += __shfl_down_sync(mask, acc1, off);
        acc2 += __shfl_down_sync(mask, acc2, off);
        acc3 += __shfl_down_sync(mask, acc3, off);
        acc4 += __shfl_down_sync(mask, acc4, off);
    }
    int lane = tid & 31, w = tid >> 5;
    if (lane == 0) {
        sred[0][w] = acc0; sred[1][w] = acc1; sred[2][w] = acc2;
        sred[3][w] = acc3; sred[4][w] = acc4;
    }
    __syncthreads();
    if (tid == 0) {
        float r0 = 0.f, r1 = 0.f, r2 = 0.f, r3 = 0.f, r4 = 0.f;
        #pragma unroll
        for (int i = 0; i < TPB / 32; i++) {
            r0 += sred[0][i]; r1 += sred[1][i]; r2 += sred[2][i];
            r3 += sred[3][i]; r4 += sred[4][i];
        }
        g_partials[blockIdx.x * 5 + 0] = r0;
        g_partials[blockIdx.x * 5 + 1] = r1;
        g_partials[blockIdx.x * 5 + 2] = r2;
        g_partials[blockIdx.x * 5 + 3] = r3;
        g_partials[blockIdx.x * 5 + 4] = r4;
    }

    // ---- ticket: last finishing block finalizes ----
    __threadfence();
    __syncthreads();
    if (tid == 0) {
        unsigned tk = atomicAdd(&g_ticket, 1u);
        amLast = (tk == (unsigned)(nb - 1));
    }
    __syncthreads();

    if (amLast) {
        float a0 = 0.f, a1 = 0.f, a2 = 0.f, a3 = 0.f, a4 = 0.f;
        for (int j = tid; j < nb; j += TPB) {
            a0 += g_partials[j * 5 + 0];
            a1 += g_partials[j * 5 + 1];
            a2 += g_partials[j * 5 + 2];
            a3 += g_partials[j * 5 + 3];
            a4 += g_partials[j * 5 + 4];
        }
        #pragma unroll
        for (int off = 16; off; off >>= 1) {
            a0 += __shfl_down_sync(mask, a0, off);
            a1 += __shfl_down_sync(mask, a1, off);
            a2 += __shfl_down_sync(mask, a2, off);
            a3 += __shfl_down_sync(mask, a3, off);
            a4 += __shfl_down_sync(mask, a4, off);
        }
        if (lane == 0) {
            sred[0][w] = a0; sred[1][w] = a1; sred[2][w] = a2;
            sred[3][w] = a3; sred[4][w] = a4;
        }
        __syncthreads();
        if (tid == 0) {
            float loc = 0.f, cobj = 0.f, cno = 0.f, ce = 0.f, nobj = 0.f;
            #pragma unroll
            for (int i = 0; i < TPB / 32; i++) {
                loc += sred[0][i]; cobj += sred[1][i]; cno += sred[2][i];
                ce  += sred[3][i]; nobj += sred[4][i];
            }
            float n   = fmaxf(nobj, 1.0f);
            float cls = ce / n;
            out[0] = (5.0f * loc + cobj + 0.5f * cno + cls) * invB;
            out[1] = loc;
            out[2] = cobj;
            out[3] = cno;
            out[4] = cls;
            __threadfence();
            g_ticket = 0;   // reset for next graph replay
        }
    }
}

extern "C" void kernel_launch(void* const* d_in, const int* in_sizes, int n_in,
                              void* d_out, int out_size)
{
    const float* pred   = (const float*)d_in[0];
    const float* target = (const float*)d_in[1];
    int n_elems = in_sizes[0];
    int n_cells = n_elems / 30;

    static bool configured = false;
    if (!configured) {
        cudaFuncSetAttribute(yolo_fused_kernel,
                             cudaFuncAttributeMaxDynamicSharedMemorySize,
                             SMEM_BYTES);
        configured = true;
    }

    long long ntiles = n_cells / TILE;

    // Perfectly balanced for the bench shape: 8192 tiles / 512 CTAs = 16 each,
    // all CTAs resident in one wave (47 KB smem -> 4 CTAs/SM, cap 592).
    int grid;
    if (ntiles >= 512 && (ntiles % 512) == 0) grid = 512;
    else {
        grid = 444;
        if (ntiles >= 1 && grid > ntiles) grid = (int)ntiles;
        if (grid < 1) grid = 1;
    }
    if (grid > GRID_MAX) grid = GRID_MAX;

    float invB = 49.0f / (float)n_cells;   // B = n_cells / 49

    yolo_fused_kernel<<<grid, TPB, SMEM_BYTES>>>(pred, target, n_cells, invB,
                                                 (float*)d_out);
}

// round 10
// speedup vs baseline: 1.1143x; 1.1143x over previous
#include <cuda_runtime.h>
#include <cstdint>

// YOLOv1 loss — single fused kernel.
// R10 = R2 hot path exactly (TILE=128 aligned, 2-stage block-coalesced
// cp.async, direct-smem compute) + perfectly balanced grid:
// 802816 cells = 128*6272 tiles = 392 CTAs * 16 tiles, zero ragged tail.

#define TPB   128
#define TILE  128
#define NF4   (TILE * 30 / 4)             // 960 float4 per tensor per stage
#define TEN_B (NF4 * 16)                  // 15360 B per tensor (128-aligned)
#define STAGE_BYTES (2 * TEN_B)           // 30720 B (pred + target)
#define NSTAGE 2
#define SMEM_BYTES (NSTAGE * STAGE_BYTES) // 61440 B
#define GRID_MAX 1024

__device__ float g_partials[GRID_MAX * 5];
__device__ unsigned int g_ticket = 0;

__device__ __forceinline__ void cp16(unsigned dst, const void* src) {
    asm volatile("cp.async.cg.shared.global [%0], [%1], 16;" :: "r"(dst), "l"(src));
}

__device__ __forceinline__ float iou_fn(float bx, float by, float bw, float bh,
                                        float tx, float ty, float tw, float th)
{
    float ax1 = bx - bw * 0.5f, ay1 = by - bh * 0.5f;
    float ax2 = bx + bw * 0.5f, ay2 = by + bh * 0.5f;
    float cx1 = tx - tw * 0.5f, cy1 = ty - th * 0.5f;
    float cx2 = tx + tw * 0.5f, cy2 = ty + th * 0.5f;
    float iw = fmaxf(fminf(ax2, cx2) - fmaxf(ax1, cx1), 0.0f);
    float ih = fmaxf(fminf(ay2, cy2) - fmaxf(ay1, cy1), 0.0f);
    float inter = iw * ih;
    float uni = bw * bh + tw * th - inter;
    return inter / fmaxf(uni, 1e-10f);
}

// Per-cell loss update reading DIRECTLY from (shared or global) memory.
// Dynamic final index -> LDS/LDG, never local memory.
__device__ __forceinline__ void cell_update(const float* P, const float* T,
                                            float& a0, float& a1, float& a2,
                                            float& a3, float& a4)
{
    float t4v  = T[4];
    float objf = (t4v == 1.0f) ? 1.0f : 0.0f;
    float noobjf = 1.0f - objf;

    float tx = T[0], ty = T[1], tw = T[2], th = T[3];
    float i0 = iou_fn(P[0], P[1], P[2], P[3], tx, ty, tw, th);
    float i1 = iou_fn(P[5], P[6], P[7], P[8], tx, ty, tw, th);

    bool b0 = (i0 > i1);   // ties -> box 1 (matches jnp.where)
    float wx = b0 ? P[0] : P[5];
    float wy = b0 ? P[1] : P[6];
    float ww = b0 ? P[2] : P[7];
    float wh = b0 ? P[3] : P[8];
    float wc = b0 ? P[4] : P[9];
    float wiou = fmaxf(i0, i1);

    float dx = wx - tx, dy = wy - ty;
    float dw = sqrtf(ww) - sqrtf(tw);
    float dh = sqrtf(wh) - sqrtf(th);
    a0 += (dx * dx + dy * dy + dw * dw + dh * dh) * objf;

    float dc = wc - wiou;
    a1 += dc * dc * objf;

    float d4 = P[4] - t4v;
    float d9 = P[9] - T[9];
    a2 += (d4 * d4 + d9 * d9) * noobjf;

    float m = -1e30f;
    #pragma unroll
    for (int c = 0; c < 20; c++) m = fmaxf(m, P[10 + c]);
    float sum = 0.0f;
    #pragma unroll
    for (int c = 0; c < 20; c++) sum += __expf(P[10 + c] - m);
    float tm = -1e30f; int targc = 0;
    #pragma unroll
    for (int c = 0; c < 20; c++) {
        float v = T[10 + c];
        if (v > tm) { tm = v; targc = c; }   // first-occurrence argmax
    }
    float ce = m + __logf(sum) - P[10 + targc];
    a3 += ce * objf;
    a4 += objf;
}

extern __shared__ char dynbuf[];   // NSTAGE x STAGE_BYTES

__global__ __launch_bounds__(TPB)
void yolo_fused_kernel(const float* __restrict__ pred,
                       const float* __restrict__ target,
                       int n_cells, float invB,
                       float* __restrict__ out)
{
    const int tid = threadIdx.x;
    const int nb  = gridDim.x;
    const long long ntiles = n_cells / TILE;
    const int rem = n_cells - (int)(ntiles * TILE);   // 0 for the bench shape

    __shared__ float sred[5][TPB / 32];
    __shared__ int amLast;

    float acc0 = 0.f, acc1 = 0.f, acc2 = 0.f, acc3 = 0.f, acc4 = 0.f;

    // Remainder cells (generic safety; 0 for the bench shape).
    if (rem && blockIdx.x == 0 && tid < rem) {
        long long c0 = ntiles * TILE + tid;
        cell_update(pred + c0 * 30, target + c0 * 30,
                    acc0, acc1, acc2, acc3, acc4);
    }

    const unsigned sbase = (unsigned)__cvta_generic_to_shared(dynbuf);

    const long long t0 = blockIdx.x;
    long long niter = 0;
    if (t0 < ntiles) niter = (ntiles - t0 + nb - 1) / nb;

    auto issue = [&](long long idx, int s) {
        long long t = t0 + idx * nb;
        const float4* p4 = (const float4*)(pred   + t * (TILE * 30));
        const float4* t4 = (const float4*)(target + t * (TILE * 30));
        unsigned base = sbase + (unsigned)(s * STAGE_BYTES);
        #pragma unroll 4
        for (int i = tid; i < NF4; i += TPB) {
            cp16(base + 16u * i,                   p4 + i);
            cp16(base + (unsigned)TEN_B + 16u * i, t4 + i);
        }
        asm volatile("cp.async.commit_group;");
    };

    // prologue: fill both stages
    if (niter > 0) issue(0, 0);
    if (niter > 1) issue(1, 1);

    for (long long it = 0; it < niter; ++it) {
        long long left = niter - 1 - it;   // groups issued beyond this one
        if (left >= 1) asm volatile("cp.async.wait_group 1;");
        else           asm volatile("cp.async.wait_group 0;");
        __syncthreads();

        int s = (int)(it & 1);
        {
            const float* sp = (const float*)(dynbuf + (size_t)s * STAGE_BYTES);
            const float* P = sp + tid * 30;
            const float* T = sp + (TEN_B / 4) + tid * 30;
            cell_update(P, T, acc0, acc1, acc2, acc3, acc4);
        }
        __syncthreads();

        long long nxt = it + 2;
        if (nxt < niter) issue(nxt, s);    // refill the stage just consumed
    }

    // ---- deterministic in-block reduction ----
    const unsigned mask = 0xffffffffu;
    #pragma unroll
    for (int off = 16; off; off >>= 1) {
        acc0 += __shfl_down_sync(mask, acc0, off);
        acc1 += __shfl_down_sync(mask, acc1, off);
        acc2 += __shfl_down_sync(mask, acc2, off);
        acc3 += __shfl_down_sync(mask, acc3, off);
        acc4 += __shfl_down_sync(mask, acc4, off);
    }
    int lane = tid & 31, w = tid >> 5;
    if (lane == 0) {
        sred[0][w] = acc0; sred[1][w] = acc1; sred[2][w] = acc2;
        sred[3][w] = acc3; sred[4][w] = acc4;
    }
    __syncthreads();
    if (tid == 0) {
        float r0 = 0.f, r1 = 0.f, r2 = 0.f, r3 = 0.f, r4 = 0.f;
        #pragma unroll
        for (int i = 0; i < TPB / 32; i++) {
            r0 += sred[0][i]; r1 += sred[1][i]; r2 += sred[2][i];
            r3 += sred[3][i]; r4 += sred[4][i];
        }
        g_partials[blockIdx.x * 5 + 0] = r0;
        g_partials[blockIdx.x * 5 + 1] = r1;
        g_partials[blockIdx.x * 5 + 2] = r2;
        g_partials[blockIdx.x * 5 + 3] = r3;
        g_partials[blockIdx.x * 5 + 4] = r4;
    }

    // ---- ticket: last finishing block finalizes ----
    __threadfence();
    __syncthreads();
    if (tid == 0) {
        unsigned tk = atomicAdd(&g_ticket, 1u);
        amLast = (tk == (unsigned)(nb - 1));
    }
    __syncthreads();

    if (amLast) {
        float a0 = 0.f, a1 = 0.f, a2 = 0.f, a3 = 0.f, a4 = 0.f;
        for (int j = tid; j < nb; j += TPB) {
            a0 += g_partials[j * 5 + 0];
            a1 += g_partials[j * 5 + 1];
            a2 += g_partials[j * 5 + 2];
            a3 += g_partials[j * 5 + 3];
            a4 += g_partials[j * 5 + 4];
        }
        #pragma unroll
        for (int off = 16; off; off >>= 1) {
            a0 += __shfl_down_sync(mask, a0, off);
            a1 += __shfl_down_sync(mask, a1, off);
            a2 += __shfl_down_sync(mask, a2, off);
            a3 += __shfl_down_sync(mask, a3, off);
            a4 += __shfl_down_sync(mask, a4, off);
        }
        if (lane == 0) {
            sred[0][w] = a0; sred[1][w] = a1; sred[2][w] = a2;
            sred[3][w] = a3; sred[4][w] = a4;
        }
        __syncthreads();
        if (tid == 0) {
            float loc = 0.f, cobj = 0.f, cno = 0.f, ce = 0.f, nobj = 0.f;
            #pragma unroll
            for (int i = 0; i < TPB / 32; i++) {
                loc += sred[0][i]; cobj += sred[1][i]; cno += sred[2][i];
                ce  += sred[3][i]; nobj += sred[4][i];
            }
            float n   = fmaxf(nobj, 1.0f);
            float cls = ce / n;
            out[0] = (5.0f * loc + cobj + 0.5f * cno + cls) * invB;
            out[1] = loc;
            out[2] = cobj;
            out[3] = cno;
            out[4] = cls;
            __threadfence();
            g_ticket = 0;   // reset for next graph replay
        }
    }
}

extern "C" void kernel_launch(void* const* d_in, const int* in_sizes, int n_in,
                              void* d_out, int out_size)
{
    const float* pred   = (const float*)d_in[0];
    const float* target = (const float*)d_in[1];
    int n_elems = in_sizes[0];
    int n_cells = n_elems / 30;

    static bool configured = false;
    if (!configured) {
        cudaFuncSetAttribute(yolo_fused_kernel,
                             cudaFuncAttributeMaxDynamicSharedMemorySize,
                             SMEM_BYTES);
        configured = true;
    }

    long long ntiles = n_cells / TILE;     // 6272 for the bench shape

    // Perfect balance when possible: 6272 = 392 * 16, all CTAs in wave 1.
    int grid;
    if (ntiles >= 392 && (ntiles % 392) == 0) grid = 392;
    else {
        grid = 444;                        // R2 fallback: 148 SMs x 3 CTAs
        if (ntiles >= 1 && grid > ntiles) grid = (int)ntiles;
        if (grid < 1) grid = 1;
    }
    if (grid > GRID_MAX) grid = GRID_MAX;

    float invB = 49.0f / (float)n_cells;   // B = n_cells / 49

    yolo_fused_kernel<<<grid, TPB, SMEM_BYTES>>>(pred, target, n_cells, invB,
                                                 (float*)d_out);
}